// round 5
// baseline (speedup 1.0000x reference)
#include <cuda_runtime.h>

// Shapes: probs (2,2,32,512,512) fp32, gt_mask (2,32,512,512) int32.
// Output: scalar fp32 = mean over all of (probs - onehot(target))^2,
// target = (gt == 1) since ignore_index=2 -> 0 and clamp [0,1].
//
// Single fused kernel, threadfence reduction. Grid-stride loop manually
// unrolled x4 with batched wide loads (12 in flight) to raise MLP and
// saturate DRAM.

constexpr int DHW      = 32 * 512 * 512;   // 8388608 = 2^23
constexpr int NGT      = 2 * DHW;          // 16777216
constexpr int VEC      = NGT / 4;          // 4194304 int4/float4 groups
constexpr int DHW4     = DHW / 4;          // 2097152 = 2^21
constexpr int BLOCKS   = 1024;
constexpr int THREADS  = 256;
constexpr int STRIDE   = BLOCKS * THREADS;         // 262144
constexpr int ITERS    = VEC / STRIDE;             // 16
constexpr int UNROLL   = 4;
constexpr int OUTER    = ITERS / UNROLL;           // 4
static_assert(OUTER * UNROLL * STRIDE == VEC, "exact tiling");

__device__ float g_partials[BLOCKS];
__device__ unsigned int g_count;   // zero-init at load; reset by last block each call

__device__ __forceinline__ float warp_sum(float v) {
    #pragma unroll
    for (int o = 16; o > 0; o >>= 1)
        v += __shfl_xor_sync(0xFFFFFFFFu, v, o);
    return v;
}

__global__ __launch_bounds__(THREADS) void mse_fused_kernel(
    const float* __restrict__ probs, const int* __restrict__ gt,
    float* __restrict__ out)
{
    const float4* __restrict__ p4 = reinterpret_cast<const float4*>(probs);
    const int4*   __restrict__ g4 = reinterpret_cast<const int4*>(gt);

    const int tid = blockIdx.x * THREADS + threadIdx.x;

    float acc = 0.0f;
    #pragma unroll
    for (int outer = 0; outer < OUTER; outer++) {
        // ---- batched load phase: 12 wide loads in flight ----
        int4   g[UNROLL];
        float4 pa[UNROLL], pb[UNROLL];
        #pragma unroll
        for (int u = 0; u < UNROLL; u++) {
            int idx = tid + (outer * UNROLL + u) * STRIDE;
            int b = idx >> 21;          // DHW4 = 2^21
            int r = idx & (DHW4 - 1);
            g[u]  = g4[idx];
            pa[u] = p4[(size_t)(2 * b    ) * DHW4 + r];  // channel 0
            pb[u] = p4[(size_t)(2 * b + 1) * DHW4 + r];  // channel 1
        }
        // ---- accumulate phase ----
        #pragma unroll
        for (int u = 0; u < UNROLL; u++) {
            float d;
            d = pa[u].x - (float)(g[u].x != 1); acc = fmaf(d, d, acc);
            d = pb[u].x - (float)(g[u].x == 1); acc = fmaf(d, d, acc);
            d = pa[u].y - (float)(g[u].y != 1); acc = fmaf(d, d, acc);
            d = pb[u].y - (float)(g[u].y == 1); acc = fmaf(d, d, acc);
            d = pa[u].z - (float)(g[u].z != 1); acc = fmaf(d, d, acc);
            d = pb[u].z - (float)(g[u].z == 1); acc = fmaf(d, d, acc);
            d = pa[u].w - (float)(g[u].w != 1); acc = fmaf(d, d, acc);
            d = pb[u].w - (float)(g[u].w == 1); acc = fmaf(d, d, acc);
        }
    }

    // Block reduction: warp shuffles -> smem -> thread 0
    __shared__ float smem[THREADS / 32];
    __shared__ bool s_last;
    acc = warp_sum(acc);
    int lane = threadIdx.x & 31;
    int wid  = threadIdx.x >> 5;
    if (lane == 0) smem[wid] = acc;
    __syncthreads();
    if (threadIdx.x == 0) {
        float v = 0.0f;
        #pragma unroll
        for (int i = 0; i < THREADS / 32; i++) v += smem[i];
        g_partials[blockIdx.x] = v;
        __threadfence();                          // publish partial
        unsigned int prev = atomicAdd(&g_count, 1u);
        s_last = (prev == (unsigned int)(gridDim.x - 1));
    }
    __syncthreads();

    if (s_last) {
        __threadfence();                          // acquire all partials
        float v = 0.0f;
        #pragma unroll
        for (int i = 0; i < BLOCKS / THREADS; i++)
            v += g_partials[threadIdx.x + i * THREADS];
        v = warp_sum(v);
        if (lane == 0) smem[wid] = v;
        __syncthreads();
        if (threadIdx.x == 0) {
            float t = 0.0f;
            #pragma unroll
            for (int i = 0; i < THREADS / 32; i++) t += smem[i];
            out[0] = t * (1.0f / 33554432.0f);    // 1 / (B*C*D*H*W)
            g_count = 0;                          // restore for next replay
        }
    }
}

extern "C" void kernel_launch(void* const* d_in, const int* in_sizes, int n_in,
                              void* d_out, int out_size)
{
    const float* probs = (const float*)d_in[0];
    const int*   gt    = (const int*)d_in[1];
    float*       out   = (float*)d_out;

    mse_fused_kernel<<<BLOCKS, THREADS>>>(probs, gt, out);
}

// round 6
// speedup vs baseline: 1.1174x; 1.1174x over previous
#include <cuda_runtime.h>

// Shapes: probs (2,2,32,512,512) fp32, gt_mask (2,32,512,512) int32.
// Output: scalar fp32 = mean over all of (probs - onehot(target))^2,
// target = (gt == 1) since ignore_index=2 -> 0 and clamp [0,1].
//
// Single kernel. Tail: one 64-bit integer atomicAdd per block carrying
// {arrival count [bits 52+], fixed-point partial sum x 2^20 [bits 0:52)}.
// Integer adds are commutative -> bitwise-deterministic across graph
// replays. The last-arriving block writes the scalar and resets state.

constexpr int DHW      = 32 * 512 * 512;   // 8388608 = 2^23
constexpr int NGT      = 2 * DHW;          // 16777216
constexpr int VEC      = NGT / 4;          // 4194304 int4/float4 groups
constexpr int DHW4     = DHW / 4;          // 2097152 = 2^21
constexpr int BLOCKS   = 1024;
constexpr int THREADS  = 256;

// Fixed-point scale: block partial <= 32768 -> *2^20 <= 2^35.
// 1024 blocks -> total <= 2^45, count lives in bits [52:63]. No overlap.
constexpr unsigned long long COUNT_ONE = 1ULL << 52;
constexpr unsigned long long SUM_MASK  = COUNT_ONE - 1ULL;

__device__ unsigned long long g_accum;  // zero-init at load; reset by last block

__device__ __forceinline__ float warp_sum(float v) {
    #pragma unroll
    for (int o = 16; o > 0; o >>= 1)
        v += __shfl_xor_sync(0xFFFFFFFFu, v, o);
    return v;
}

__global__ __launch_bounds__(THREADS) void mse_fused_kernel(
    const float* __restrict__ probs, const int* __restrict__ gt,
    float* __restrict__ out)
{
    const float4* __restrict__ p4 = reinterpret_cast<const float4*>(probs);
    const int4*   __restrict__ g4 = reinterpret_cast<const int4*>(gt);

    float acc = 0.0f;
    const int stride = gridDim.x * blockDim.x;
    for (int idx = blockIdx.x * blockDim.x + threadIdx.x; idx < VEC; idx += stride) {
        int4 g = g4[idx];
        int b = idx >> 21;            // DHW4 = 2^21
        int r = idx & (DHW4 - 1);
        // probs layout (B, C, D, H, W): channel stride = DHW
        float4 p0 = p4[(size_t)(2 * b    ) * DHW4 + r];  // c = 0
        float4 p1 = p4[(size_t)(2 * b + 1) * DHW4 + r];  // c = 1

        // onehot: oh0 = (gt != 1), oh1 = (gt == 1)
        float d;
        d = p0.x - (float)(g.x != 1); acc = fmaf(d, d, acc);
        d = p1.x - (float)(g.x == 1); acc = fmaf(d, d, acc);
        d = p0.y - (float)(g.y != 1); acc = fmaf(d, d, acc);
        d = p1.y - (float)(g.y == 1); acc = fmaf(d, d, acc);
        d = p0.z - (float)(g.z != 1); acc = fmaf(d, d, acc);
        d = p1.z - (float)(g.z == 1); acc = fmaf(d, d, acc);
        d = p0.w - (float)(g.w != 1); acc = fmaf(d, d, acc);
        d = p1.w - (float)(g.w == 1); acc = fmaf(d, d, acc);
    }

    // Block reduction: warp shuffles -> smem -> thread 0
    __shared__ float smem[THREADS / 32];
    acc = warp_sum(acc);
    int lane = threadIdx.x & 31;
    int wid  = threadIdx.x >> 5;
    if (lane == 0) smem[wid] = acc;
    __syncthreads();

    if (threadIdx.x == 0) {
        float v = 0.0f;
        #pragma unroll
        for (int i = 0; i < THREADS / 32; i++) v += smem[i];

        // Fixed-point encode (round to nearest) + arrival count in one atom.
        unsigned long long mine =
            COUNT_ONE | (unsigned long long)(v * 1048576.0f + 0.5f);
        unsigned long long prev = atomicAdd(&g_accum, mine);
        unsigned long long now  = prev + mine;

        if ((now >> 52) == (unsigned long long)gridDim.x) {
            // Last block: now's low bits hold the exact total.
            float total = (float)((double)(now & SUM_MASK) * 0x1p-45);
            out[0] = total;                 // 2^-20 (scale) * 2^-25 (1/N)
            g_accum = 0ULL;                 // restore invariant for next replay
        }
    }
}

extern "C" void kernel_launch(void* const* d_in, const int* in_sizes, int n_in,
                              void* d_out, int out_size)
{
    const float* probs = (const float*)d_in[0];
    const int*   gt    = (const int*)d_in[1];
    float*       out   = (float*)d_out;

    mse_fused_kernel<<<BLOCKS, THREADS>>>(probs, gt, out);
}

// round 7
// speedup vs baseline: 1.1611x; 1.0391x over previous
#include <cuda_runtime.h>

// Shapes: probs (2,2,32,512,512) fp32, gt_mask (2,32,512,512) int32.
// Output: scalar fp32 = mean over all of (probs - onehot(target))^2,
// target = (gt == 1) since ignore_index=2 -> 0 and clamp [0,1].
//
// Single kernel; grid = 148 SMs x 8 CTAs = 1184 (full residency).
// Streaming loads (__ldcs) for the read-once 192 MiB working set.
// Tail: one packed 64-bit atomicAdd per block {count[52:], fixedpoint
// sum x 2^20 [0:52)}; integer adds -> bitwise deterministic replays.

constexpr int DHW      = 32 * 512 * 512;   // 8388608 = 2^23
constexpr int NGT      = 2 * DHW;          // 16777216
constexpr int VEC      = NGT / 4;          // 4194304 int4/float4 groups
constexpr int DHW4     = DHW / 4;          // 2097152 = 2^21
constexpr int BLOCKS   = 1184;             // 148 SMs * 8 CTAs
constexpr int THREADS  = 256;

// Fixed-point: block partial <= ~28000 -> *2^20 < 2^35; 1184 blocks -> < 2^46.
// Count lives in bits [52:]; 1184 * COUNT_ONE fits in [52:63]. No overlap.
constexpr unsigned long long COUNT_ONE = 1ULL << 52;
constexpr unsigned long long SUM_MASK  = COUNT_ONE - 1ULL;

__device__ unsigned long long g_accum;  // zero-init at load; reset by last block

__device__ __forceinline__ float warp_sum(float v) {
    #pragma unroll
    for (int o = 16; o > 0; o >>= 1)
        v += __shfl_xor_sync(0xFFFFFFFFu, v, o);
    return v;
}

__global__ __launch_bounds__(THREADS) void mse_fused_kernel(
    const float* __restrict__ probs, const int* __restrict__ gt,
    float* __restrict__ out)
{
    const float4* __restrict__ p4 = reinterpret_cast<const float4*>(probs);
    const int4*   __restrict__ g4 = reinterpret_cast<const int4*>(gt);

    float acc = 0.0f;
    const int stride = gridDim.x * blockDim.x;
    for (int idx = blockIdx.x * blockDim.x + threadIdx.x; idx < VEC; idx += stride) {
        int4 g = __ldcs(&g4[idx]);
        int b = idx >> 21;            // DHW4 = 2^21
        int r = idx & (DHW4 - 1);
        // probs layout (B, C, D, H, W): channel stride = DHW
        float4 p0 = __ldcs(&p4[(size_t)(2 * b    ) * DHW4 + r]);  // c = 0
        float4 p1 = __ldcs(&p4[(size_t)(2 * b + 1) * DHW4 + r]);  // c = 1

        // onehot: oh0 = (gt != 1), oh1 = (gt == 1)
        float d;
        d = p0.x - (float)(g.x != 1); acc = fmaf(d, d, acc);
        d = p1.x - (float)(g.x == 1); acc = fmaf(d, d, acc);
        d = p0.y - (float)(g.y != 1); acc = fmaf(d, d, acc);
        d = p1.y - (float)(g.y == 1); acc = fmaf(d, d, acc);
        d = p0.z - (float)(g.z != 1); acc = fmaf(d, d, acc);
        d = p1.z - (float)(g.z == 1); acc = fmaf(d, d, acc);
        d = p0.w - (float)(g.w != 1); acc = fmaf(d, d, acc);
        d = p1.w - (float)(g.w == 1); acc = fmaf(d, d, acc);
    }

    // Block reduction: warp shuffles -> smem -> thread 0
    __shared__ float smem[THREADS / 32];
    acc = warp_sum(acc);
    int lane = threadIdx.x & 31;
    int wid  = threadIdx.x >> 5;
    if (lane == 0) smem[wid] = acc;
    __syncthreads();

    if (threadIdx.x == 0) {
        float v = 0.0f;
        #pragma unroll
        for (int i = 0; i < THREADS / 32; i++) v += smem[i];

        // Fixed-point encode (round to nearest) + arrival count, one atom.
        unsigned long long mine =
            COUNT_ONE | (unsigned long long)(v * 1048576.0f + 0.5f);
        unsigned long long prev = atomicAdd(&g_accum, mine);
        unsigned long long now  = prev + mine;

        if ((now >> 52) == (unsigned long long)gridDim.x) {
            // Last block: low bits hold the exact fixed-point total.
            float total = (float)((double)(now & SUM_MASK) * 0x1p-45);
            out[0] = total;                 // 2^-20 (scale) * 2^-25 (1/N)
            g_accum = 0ULL;                 // restore invariant for next replay
        }
    }
}

extern "C" void kernel_launch(void* const* d_in, const int* in_sizes, int n_in,
                              void* d_out, int out_size)
{
    const float* probs = (const float*)d_in[0];
    const int*   gt    = (const int*)d_in[1];
    float*       out   = (float*)d_out;

    mse_fused_kernel<<<BLOCKS, THREADS>>>(probs, gt, out);
}